// round 2
// baseline (speedup 1.0000x reference)
#include <cuda_runtime.h>
#include <math.h>

// Problem shapes (fixed)
#define CB 4
#define CS 2048
#define CE 2048
#define CH 16
#define CD 128
#define M_TOT (CB*CS)      // 8192
#define NQKV  (3*CE)       // 6144

// Scratch (device globals: no allocation allowed in kernel_launch)
__device__ float g_qkv[(size_t)M_TOT * NQKV];   // [8192, 6144]
__device__ float g_o[(size_t)M_TOT * CE];       // [8192, 2048] (head-contiguous layout)

// ---------------------------------------------------------------------------
// SGEMM: C[M,N] = A[M,K] @ B[K,N], all row-major fp32.
// 128x128 block tile, K-tile 8, 256 threads, 8x8 micro-tile.
// Column micro-mapping split as {tx*4..+3, 64+tx*4..+3} for conflict-free
// Bs float4 reads.
// ---------------------------------------------------------------------------
__global__ __launch_bounds__(256, 2)
void sgemm128(const float* __restrict__ A, const float* __restrict__ B,
              float* __restrict__ C, int M, int N, int K)
{
    __shared__ float As[8][128];
    __shared__ float Bs[8][128];

    const int tid = threadIdx.x;
    const int tx = tid & 15;
    const int ty = tid >> 4;
    const int bm = blockIdx.y * 128;
    const int bn = blockIdx.x * 128;

    const int arow = tid >> 1;          // 0..127
    const int acol = (tid & 1) << 2;    // 0 or 4
    const int brow = tid >> 5;          // 0..7
    const int bcol = (tid & 31) << 2;   // 0..124

    const float* Ag = A + (size_t)(bm + arow) * K + acol;
    const float* Bg = B + (size_t)brow * N + bn + bcol;

    float acc[8][8];
    #pragma unroll
    for (int i = 0; i < 8; i++)
        #pragma unroll
        for (int j = 0; j < 8; j++) acc[i][j] = 0.0f;

    for (int k0 = 0; k0 < K; k0 += 8) {
        float4 av = *(const float4*)Ag;
        float4 bv = *(const float4*)Bg;
        Ag += 8;
        Bg += (size_t)8 * N;

        __syncthreads();   // previous compute done before overwriting smem
        As[acol + 0][arow] = av.x;
        As[acol + 1][arow] = av.y;
        As[acol + 2][arow] = av.z;
        As[acol + 3][arow] = av.w;
        *(float4*)&Bs[brow][bcol] = bv;
        __syncthreads();

        #pragma unroll
        for (int kk = 0; kk < 8; kk++) {
            float4 a0 = *(const float4*)&As[kk][ty * 8];
            float4 a1 = *(const float4*)&As[kk][ty * 8 + 4];
            float4 b0 = *(const float4*)&Bs[kk][tx * 4];
            float4 b1 = *(const float4*)&Bs[kk][64 + tx * 4];
            float ar[8] = {a0.x, a0.y, a0.z, a0.w, a1.x, a1.y, a1.z, a1.w};
            float br[8] = {b0.x, b0.y, b0.z, b0.w, b1.x, b1.y, b1.z, b1.w};
            #pragma unroll
            for (int i = 0; i < 8; i++)
                #pragma unroll
                for (int j = 0; j < 8; j++)
                    acc[i][j] += ar[i] * br[j];
        }
    }

    float* Cp = C + (size_t)(bm + ty * 8) * N + bn;
    #pragma unroll
    for (int i = 0; i < 8; i++) {
        *(float4*)(Cp + (size_t)i * N + tx * 4) =
            make_float4(acc[i][0], acc[i][1], acc[i][2], acc[i][3]);
        *(float4*)(Cp + (size_t)i * N + 64 + tx * 4) =
            make_float4(acc[i][4], acc[i][5], acc[i][6], acc[i][7]);
    }
}

// ---------------------------------------------------------------------------
// Flash attention, fp32, causal. One block = 128 query rows of one (b,h).
// Br = Bc = 128, D = 128. 256 threads (16x16).
//  S micro-tile: rows ty*8+i, key-cols tx*8+j  (8x8)
//  O micro-tile: rows ty*8+i, d-cols {tx*4+j, 64+tx*4+j}
// smem: sQ (plain) | sK (xor-swizzled; reused as P, plain) | sV (plain)
// Q/K/V read directly from g_qkv with the "raw reshape" addressing:
//   row(b,h,s) = b*2048 + h*128 + (s>>4), colbase = (s&15)*128  (+off 0/2048/4096)
// ---------------------------------------------------------------------------
#define FLASH_SMEM (3 * 128 * 128 * 4)   // 196608 B

__global__ __launch_bounds__(256, 1)
void flash_attn(const float* __restrict__ qkv, float* __restrict__ o)
{
    extern __shared__ float sm[];
    float* sQ = sm;                 // [128][128]
    float* sK = sm + 128 * 128;     // [128][128] swizzled K, later P (plain)
    float* sV = sm + 2 * 128 * 128; // [128][128]

    const int tid = threadIdx.x;
    const int tx = tid & 15;
    const int ty = tid >> 4;
    const int qt = blockIdx.x;   // query tile 0..15
    const int h  = blockIdx.y;
    const int b  = blockIdx.z;

    // 1/sqrt(128) * log2(e): fold softmax scale + base-2 exp into Q
    const float SC = 0.08838834764831845f * 1.4426950408889634f;

    // ---- load Q tile (scaled) ----
    for (int i = tid; i < 128 * 32; i += 256) {
        int r  = i >> 5;       // 0..127
        int d4 = i & 31;       // float4 index 0..31
        const float* src = qkv
            + (size_t)(b * 2048 + h * 128 + qt * 8 + (r >> 4)) * 6144
            + ((r & 15) << 7) + (d4 << 2);
        float4 v = *(const float4*)src;
        v.x *= SC; v.y *= SC; v.z *= SC; v.w *= SC;
        *(float4*)&sQ[r * 128 + (d4 << 2)] = v;
    }

    float Oa[8][8];
    #pragma unroll
    for (int i = 0; i < 8; i++)
        #pragma unroll
        for (int j = 0; j < 8; j++) Oa[i][j] = 0.0f;
    float mrow[8], lrow[8];
    #pragma unroll
    for (int i = 0; i < 8; i++) { mrow[i] = -1e30f; lrow[i] = 0.0f; }

    const int kxor = tx & 7;  // read-side swizzle for K rows c=tx*8+j

    for (int kt = 0; kt <= qt; kt++) {
        __syncthreads();  // previous PV (and Q load) complete

        // ---- load K,V tiles ----
        for (int i = tid; i < 128 * 32; i += 256) {
            int r  = i >> 5;
            int d4 = i & 31;
            size_t grow = (size_t)(b * 2048 + h * 128 + kt * 8 + (r >> 4)) * 6144
                        + ((r & 15) << 7) + (d4 << 2);
            float4 kv = *(const float4*)(qkv + grow + 2048);
            float4 vv = *(const float4*)(qkv + grow + 4096);
            int kd4 = d4 ^ ((r >> 3) & 7);                 // xor swizzle
            *(float4*)&sK[r * 128 + (kd4 << 2)] = kv;
            *(float4*)&sV[r * 128 + (d4 << 2)] = vv;
        }
        __syncthreads();

        // ---- S = Q @ K^T  (scaled, base-2 units) ----
        float s[8][8];
        #pragma unroll
        for (int i = 0; i < 8; i++)
            #pragma unroll
            for (int j = 0; j < 8; j++) s[i][j] = 0.0f;

        #pragma unroll 4
        for (int d4 = 0; d4 < 32; d4++) {
            float4 q[8];
            #pragma unroll
            for (int i = 0; i < 8; i++)
                q[i] = *(const float4*)&sQ[(ty * 8 + i) * 128 + (d4 << 2)];
            #pragma unroll
            for (int j = 0; j < 8; j++) {
                float4 kv = *(const float4*)&sK[(tx * 8 + j) * 128 + ((d4 ^ kxor) << 2)];
                #pragma unroll
                for (int i = 0; i < 8; i++)
                    s[i][j] += q[i].x * kv.x + q[i].y * kv.y
                             + q[i].z * kv.z + q[i].w * kv.w;
            }
        }

        // ---- causal mask on the diagonal tile ----
        if (kt == qt) {
            #pragma unroll
            for (int i = 0; i < 8; i++)
                #pragma unroll
                for (int j = 0; j < 8; j++)
                    if (tx * 8 + j > ty * 8 + i) s[i][j] = -1e30f;
        }

        __syncthreads();  // all threads done reading sK before P overwrite

        // ---- online softmax + write P into sK's space ----
        #pragma unroll
        for (int i = 0; i < 8; i++) {
            float rm = s[i][0];
            #pragma unroll
            for (int j = 1; j < 8; j++) rm = fmaxf(rm, s[i][j]);
            #pragma unroll
            for (int off = 8; off >= 1; off >>= 1)
                rm = fmaxf(rm, __shfl_xor_sync(0xffffffffu, rm, off, 16));
            float mnew = fmaxf(mrow[i], rm);
            float corr = exp2f(mrow[i] - mnew);
            mrow[i] = mnew;
            float rs = 0.0f;
            #pragma unroll
            for (int j = 0; j < 8; j++) {
                float p = exp2f(s[i][j] - mnew);
                s[i][j] = p;
                rs += p;
            }
            #pragma unroll
            for (int off = 8; off >= 1; off >>= 1)
                rs += __shfl_xor_sync(0xffffffffu, rs, off, 16);
            lrow[i] = lrow[i] * corr + rs;
            #pragma unroll
            for (int j = 0; j < 8; j++) Oa[i][j] *= corr;
            *(float4*)&sK[(ty * 8 + i) * 128 + tx * 8] =
                make_float4(s[i][0], s[i][1], s[i][2], s[i][3]);
            *(float4*)&sK[(ty * 8 + i) * 128 + tx * 8 + 4] =
                make_float4(s[i][4], s[i][5], s[i][6], s[i][7]);
        }
        __syncthreads();

        // ---- O += P @ V ----
        #pragma unroll 4
        for (int c = 0; c < 128; c++) {
            float4 va = *(const float4*)&sV[c * 128 + tx * 4];
            float4 vb = *(const float4*)&sV[c * 128 + 64 + tx * 4];
            #pragma unroll
            for (int i = 0; i < 8; i++) {
                float p = sK[(ty * 8 + i) * 128 + c];
                Oa[i][0] += p * va.x; Oa[i][1] += p * va.y;
                Oa[i][2] += p * va.z; Oa[i][3] += p * va.w;
                Oa[i][4] += p * vb.x; Oa[i][5] += p * vb.y;
                Oa[i][6] += p * vb.z; Oa[i][7] += p * vb.w;
            }
        }
    }

    // ---- normalize + write O (head-contiguous layout) ----
    #pragma unroll
    for (int i = 0; i < 8; i++) {
        float inv = 1.0f / lrow[i];
        int srow = qt * 128 + ty * 8 + i;
        float* dst = o + (((size_t)(b * 16 + h) * 2048 + srow) << 7);
        *(float4*)(dst + tx * 4) = make_float4(
            Oa[i][0] * inv, Oa[i][1] * inv, Oa[i][2] * inv, Oa[i][3] * inv);
        *(float4*)(dst + 64 + tx * 4) = make_float4(
            Oa[i][4] * inv, Oa[i][5] * inv, Oa[i][6] * inv, Oa[i][7] * inv);
    }
}

// ---------------------------------------------------------------------------
extern "C" void kernel_launch(void* const* d_in, const int* in_sizes, int n_in,
                              void* d_out, int out_size)
{
    (void)in_sizes; (void)n_in; (void)out_size;
    const float* x    = (const float*)d_in[0];
    const float* wqkv = (const float*)d_in[1];
    const float* wout = (const float*)d_in[2];
    float* out = (float*)d_out;

    // Non-stream runtime APIs: execute immediately, legal under graph capture.
    float *qkv_ptr = nullptr, *o_ptr = nullptr;
    cudaGetSymbolAddress((void**)&qkv_ptr, g_qkv);
    cudaGetSymbolAddress((void**)&o_ptr, g_o);
    cudaFuncSetAttribute(flash_attn,
                         cudaFuncAttributeMaxDynamicSharedMemorySize, FLASH_SMEM);

    // 1) QKV projection: [8192,2048] @ [2048,6144]
    dim3 g1(NQKV / 128, M_TOT / 128);
    sgemm128<<<g1, 256>>>(x, wqkv, qkv_ptr, M_TOT, NQKV, CE);

    // 2) causal attention per (b,h), head-contiguous I/O
    dim3 gf(CS / 128, CH, CB);
    flash_attn<<<gf, 256, FLASH_SMEM>>>(qkv_ptr, o_ptr);

    // 3) output projection: [8192,2048] @ [2048,2048]
    dim3 g2(CE / 128, M_TOT / 128);
    sgemm128<<<g2, 256>>>(o_ptr, wout, out, M_TOT, CE, CE);
}

// round 5
// speedup vs baseline: 1.7111x; 1.7111x over previous
#include <cuda_runtime.h>
#include <cuda_bf16.h>
#include <cstdint>
#include <math.h>

#define M_TOT 8192
#define NQKV  6144
#define GK    2048

// ---------------- device scratch (no allocs allowed) ----------------
__device__ float         g_qkv[(size_t)M_TOT * NQKV];   // fp32 QKV for attention
__device__ __nv_bfloat16 g_xh[(size_t)M_TOT * GK];
__device__ __nv_bfloat16 g_xl[(size_t)M_TOT * GK];
__device__ __nv_bfloat16 g_wqh[(size_t)NQKV * GK];      // W_qkv^T [6144,2048]
__device__ __nv_bfloat16 g_wql[(size_t)NQKV * GK];
__device__ __nv_bfloat16 g_woh[(size_t)GK * GK];        // W_out^T [2048,2048]
__device__ __nv_bfloat16 g_wol[(size_t)GK * GK];
__device__ __nv_bfloat16 g_oh[(size_t)M_TOT * GK];      // attention out hi/lo
__device__ __nv_bfloat16 g_ol[(size_t)M_TOT * GK];

// ---------------- helpers ----------------
static __device__ __forceinline__ void split2u(float a, float b, uint32_t& h, uint32_t& l) {
    __nv_bfloat16 ha = __float2bfloat16(a);
    __nv_bfloat16 hb = __float2bfloat16(b);
    __nv_bfloat16 la = __float2bfloat16(a - __bfloat162float(ha));
    __nv_bfloat16 lb = __float2bfloat16(b - __bfloat162float(hb));
    h = (uint32_t)__bfloat16_as_ushort(ha) | ((uint32_t)__bfloat16_as_ushort(hb) << 16);
    l = (uint32_t)__bfloat16_as_ushort(la) | ((uint32_t)__bfloat16_as_ushort(lb) << 16);
}

#define CPA16(dst, src) \
    asm volatile("cp.async.cg.shared.global [%0], [%1], 16;" :: "r"(dst), "l"(src))
#define CPA_COMMIT() asm volatile("cp.async.commit_group;")
#define CPA_WAIT1()  asm volatile("cp.async.wait_group 1;")
#define CPA_WAIT0()  asm volatile("cp.async.wait_group 0;")

#define MMA16816(ac, a0, a1, a2, a3, b0, b1) \
    asm volatile("mma.sync.aligned.m16n8k16.row.col.f32.bf16.bf16.f32 " \
        "{%0,%1,%2,%3},{%4,%5,%6,%7},{%8,%9},{%0,%1,%2,%3};" \
        : "+f"((ac)[0]), "+f"((ac)[1]), "+f"((ac)[2]), "+f"((ac)[3]) \
        : "r"(a0), "r"(a1), "r"(a2), "r"(a3), "r"(b0), "r"(b1))

// ---------------- conversion kernels ----------------
__global__ void ksplit(const float* __restrict__ in, __nv_bfloat16* __restrict__ hi,
                       __nv_bfloat16* __restrict__ lo, int n4)
{
    int i = blockIdx.x * blockDim.x + threadIdx.x;
    if (i >= n4) return;
    float4 v = ((const float4*)in)[i];
    uint2 h, l;
    split2u(v.x, v.y, h.x, l.x);
    split2u(v.z, v.w, h.y, l.y);
    ((uint2*)hi)[i] = h;
    ((uint2*)lo)[i] = l;
}

// in [K, N] row-major -> out^T [N, K] hi/lo bf16
__global__ void ksplitT(const float* __restrict__ in, __nv_bfloat16* __restrict__ hiT,
                        __nv_bfloat16* __restrict__ loT, int K, int N)
{
    __shared__ float t[32][33];
    int n0 = blockIdx.x * 32, k0 = blockIdx.y * 32;
    int tx = threadIdx.x, ty = threadIdx.y;   // 32 x 8
    #pragma unroll
    for (int j = 0; j < 32; j += 8)
        t[ty + j][tx] = in[(size_t)(k0 + ty + j) * N + n0 + tx];
    __syncthreads();
    #pragma unroll
    for (int j = 0; j < 32; j += 8) {
        float v = t[tx][ty + j];              // k = k0+tx, n = n0+ty+j
        __nv_bfloat16 h = __float2bfloat16(v);
        __nv_bfloat16 l = __float2bfloat16(v - __bfloat162float(h));
        size_t oi = (size_t)(n0 + ty + j) * K + k0 + tx;
        hiT[oi] = h;
        loT[oi] = l;
    }
}

// ---------------- mma.sync bf16x3 GEMM ----------------
// C[M,N] = (Ah+Al) @ (Bh+Bl)^T (dropping lo*lo).
// A: [M,2048] K-major, B: [Ntot,2048] K-major (= W^T). Row-major fp32 C.
// Block 128x128x32, 256 thr, 8 warps (2M x 4N -> 64x32 warp tiles),
// 2-stage cp.async. Smem rows padded to 80B -> conflict-free LDS.32 frags.
#define SROW    80
#define TILE_B  (128 * SROW)      // 10240
#define STAGE_B (4 * TILE_B)      // 40960: Ah | Al | Bh | Bl
#define GSMEM   (2 * STAGE_B)     // 81920

__global__ __launch_bounds__(256)
void gemm_mma_bf16x3(const __nv_bfloat16* __restrict__ Ah,
                     const __nv_bfloat16* __restrict__ Al,
                     const __nv_bfloat16* __restrict__ Bh,
                     const __nv_bfloat16* __restrict__ Bl,
                     float* __restrict__ C, int ldc)
{
    extern __shared__ __align__(16) char smem[];
    const uint32_t sbase = (uint32_t)__cvta_generic_to_shared(smem);
    const int tid  = threadIdx.x;
    const int warp = tid >> 5, lane = tid & 31;
    const int m0 = blockIdx.y * 128, n0 = blockIdx.x * 128;
    const int wm = (warp & 1) * 64, wn = (warp >> 1) * 32;

    // per-thread load map: 8 chunks of 16B per stage
    // i in [0,2048): sub = i>>9 (Ah,Al,Bh,Bl), r = (i&511)>>2, c = i&3
    auto issue = [&](int st, int k0) {
        uint32_t dbase = sbase + st * STAGE_B;
        #pragma unroll
        for (int t = 0; t < 8; t++) {
            int i = tid + t * 256;
            int sub = i >> 9;
            int j = i & 511;
            int r = j >> 2, c = j & 3;
            const __nv_bfloat16* g =
                (sub == 0) ? Ah + (size_t)(m0 + r) * GK + k0 + c * 8 :
                (sub == 1) ? Al + (size_t)(m0 + r) * GK + k0 + c * 8 :
                (sub == 2) ? Bh + (size_t)(n0 + r) * GK + k0 + c * 8 :
                             Bl + (size_t)(n0 + r) * GK + k0 + c * 8;
            uint32_t d = dbase + sub * TILE_B + r * SROW + c * 16;
            CPA16(d, (const void*)g);
        }
        CPA_COMMIT();
    };

    float acc[4][4][4];
    #pragma unroll
    for (int mi = 0; mi < 4; mi++)
        #pragma unroll
        for (int ni = 0; ni < 4; ni++)
            #pragma unroll
            for (int q = 0; q < 4; q++) acc[mi][ni][q] = 0.0f;

    issue(0, 0);

    const int lr = lane >> 2;          // 0..7
    const int lc4 = (lane & 3) * 4;    // byte offset of k-pair

    for (int ch = 0; ch < 64; ch++) {
        int buf = ch & 1;
        if (ch < 63) { issue(buf ^ 1, (ch + 1) * 32); CPA_WAIT1(); }
        else         { CPA_WAIT0(); }
        __syncthreads();

        const char* sb  = smem + buf * STAGE_B;
        const char* sAh = sb;
        const char* sAl = sb + TILE_B;
        const char* sBh = sb + 2 * TILE_B;
        const char* sBl = sb + 3 * TILE_B;

        #pragma unroll
        for (int k16 = 0; k16 < 32; k16 += 16) {
            const int kb = k16 * 2 + lc4;
            // B fragments (hi+lo) for 4 n8 tiles
            uint32_t bh[4][2], bl[4][2];
            #pragma unroll
            for (int ni = 0; ni < 4; ni++) {
                int off = (wn + ni * 8 + lr) * SROW + kb;
                bh[ni][0] = *(const uint32_t*)(sBh + off);
                bh[ni][1] = *(const uint32_t*)(sBh + off + 16);
                bl[ni][0] = *(const uint32_t*)(sBl + off);
                bl[ni][1] = *(const uint32_t*)(sBl + off + 16);
            }
            #pragma unroll
            for (int mi = 0; mi < 4; mi++) {
                int off = (wm + mi * 16 + lr) * SROW + kb;
                uint32_t ah0 = *(const uint32_t*)(sAh + off);
                uint32_t ah1 = *(const uint32_t*)(sAh + off + 8 * SROW);
                uint32_t ah2 = *(const uint32_t*)(sAh + off + 16);
                uint32_t ah3 = *(const uint32_t*)(sAh + off + 8 * SROW + 16);
                uint32_t al0 = *(const uint32_t*)(sAl + off);
                uint32_t al1 = *(const uint32_t*)(sAl + off + 8 * SROW);
                uint32_t al2 = *(const uint32_t*)(sAl + off + 16);
                uint32_t al3 = *(const uint32_t*)(sAl + off + 8 * SROW + 16);
                #pragma unroll
                for (int ni = 0; ni < 4; ni++) {
                    MMA16816(acc[mi][ni], ah0, ah1, ah2, ah3, bh[ni][0], bh[ni][1]);
                    MMA16816(acc[mi][ni], ah0, ah1, ah2, ah3, bl[ni][0], bl[ni][1]);
                    MMA16816(acc[mi][ni], al0, al1, al2, al3, bh[ni][0], bh[ni][1]);
                }
            }
        }
        __syncthreads();
    }

    // epilogue: c0,c1 -> (row, col..col+1); c2,c3 -> (row+8, col..col+1)
    #pragma unroll
    for (int mi = 0; mi < 4; mi++) {
        int row = m0 + wm + mi * 16 + lr;
        #pragma unroll
        for (int ni = 0; ni < 4; ni++) {
            int col = n0 + wn + ni * 8 + (lane & 3) * 2;
            float* p0 = C + (size_t)row * ldc + col;
            float* p1 = C + (size_t)(row + 8) * ldc + col;
            p0[0] = acc[mi][ni][0]; p0[1] = acc[mi][ni][1];
            p1[0] = acc[mi][ni][2]; p1[1] = acc[mi][ni][3];
        }
    }
}

// ---------------- flash attention (fp32), bf16 hi/lo output ----------------
#define FLASH_SMEM (3 * 128 * 128 * 4)

__global__ __launch_bounds__(256, 1)
void flash_attn(const float* __restrict__ qkv,
                __nv_bfloat16* __restrict__ oh, __nv_bfloat16* __restrict__ ol)
{
    extern __shared__ float sm[];
    float* sQ = sm;
    float* sK = sm + 128 * 128;
    float* sV = sm + 2 * 128 * 128;

    const int tid = threadIdx.x;
    const int tx = tid & 15;
    const int ty = tid >> 4;
    const int qt = blockIdx.x;
    const int h  = blockIdx.y;
    const int b  = blockIdx.z;
    const float SC = 0.08838834764831845f * 1.4426950408889634f;

    for (int i = tid; i < 128 * 32; i += 256) {
        int r = i >> 5, d4 = i & 31;
        const float* src = qkv
            + (size_t)(b * 2048 + h * 128 + qt * 8 + (r >> 4)) * 6144
            + ((r & 15) << 7) + (d4 << 2);
        float4 v = *(const float4*)src;
        v.x *= SC; v.y *= SC; v.z *= SC; v.w *= SC;
        *(float4*)&sQ[r * 128 + (d4 << 2)] = v;
    }

    float Oa[8][8];
    #pragma unroll
    for (int i = 0; i < 8; i++)
        #pragma unroll
        for (int j = 0; j < 8; j++) Oa[i][j] = 0.0f;
    float mrow[8], lrow[8];
    #pragma unroll
    for (int i = 0; i < 8; i++) { mrow[i] = -1e30f; lrow[i] = 0.0f; }

    const int kxor = tx & 7;

    for (int kt = 0; kt <= qt; kt++) {
        __syncthreads();
        for (int i = tid; i < 128 * 32; i += 256) {
            int r = i >> 5, d4 = i & 31;
            size_t grow = (size_t)(b * 2048 + h * 128 + kt * 8 + (r >> 4)) * 6144
                        + ((r & 15) << 7) + (d4 << 2);
            float4 kv = *(const float4*)(qkv + grow + 2048);
            float4 vv = *(const float4*)(qkv + grow + 4096);
            int kd4 = d4 ^ ((r >> 3) & 7);
            *(float4*)&sK[r * 128 + (kd4 << 2)] = kv;
            *(float4*)&sV[r * 128 + (d4 << 2)] = vv;
        }
        __syncthreads();

        float s[8][8];
        #pragma unroll
        for (int i = 0; i < 8; i++)
            #pragma unroll
            for (int j = 0; j < 8; j++) s[i][j] = 0.0f;

        #pragma unroll 4
        for (int d4 = 0; d4 < 32; d4++) {
            float4 q[8];
            #pragma unroll
            for (int i = 0; i < 8; i++)
                q[i] = *(const float4*)&sQ[(ty * 8 + i) * 128 + (d4 << 2)];
            #pragma unroll
            for (int j = 0; j < 8; j++) {
                float4 kv = *(const float4*)&sK[(tx * 8 + j) * 128 + ((d4 ^ kxor) << 2)];
                #pragma unroll
                for (int i = 0; i < 8; i++)
                    s[i][j] += q[i].x * kv.x + q[i].y * kv.y
                             + q[i].z * kv.z + q[i].w * kv.w;
            }
        }

        if (kt == qt) {
            #pragma unroll
            for (int i = 0; i < 8; i++)
                #pragma unroll
                for (int j = 0; j < 8; j++)
                    if (tx * 8 + j > ty * 8 + i) s[i][j] = -1e30f;
        }

        __syncthreads();

        #pragma unroll
        for (int i = 0; i < 8; i++) {
            float rm = s[i][0];
            #pragma unroll
            for (int j = 1; j < 8; j++) rm = fmaxf(rm, s[i][j]);
            #pragma unroll
            for (int off = 8; off >= 1; off >>= 1)
                rm = fmaxf(rm, __shfl_xor_sync(0xffffffffu, rm, off, 16));
            float mnew = fmaxf(mrow[i], rm);
            float corr = exp2f(mrow[i] - mnew);
            mrow[i] = mnew;
            float rs = 0.0f;
            #pragma unroll
            for (int j = 0; j < 8; j++) {
                float p = exp2f(s[i][j] - mnew);
                s[i][j] = p;
                rs += p;
            }
            #pragma unroll
            for (int off = 8; off >= 1; off >>= 1)
                rs += __shfl_xor_sync(0xffffffffu, rs, off, 16);
            lrow[i] = lrow[i] * corr + rs;
            #pragma unroll
            for (int j = 0; j < 8; j++) Oa[i][j] *= corr;
            *(float4*)&sK[(ty * 8 + i) * 128 + tx * 8] =
                make_float4(s[i][0], s[i][1], s[i][2], s[i][3]);
            *(float4*)&sK[(ty * 8 + i) * 128 + tx * 8 + 4] =
                make_float4(s[i][4], s[i][5], s[i][6], s[i][7]);
        }
        __syncthreads();

        #pragma unroll 4
        for (int c = 0; c < 128; c++) {
            float4 va = *(const float4*)&sV[c * 128 + tx * 4];
            float4 vb = *(const float4*)&sV[c * 128 + 64 + tx * 4];
            #pragma unroll
            for (int i = 0; i < 8; i++) {
                float p = sK[(ty * 8 + i) * 128 + c];
                Oa[i][0] += p * va.x; Oa[i][1] += p * va.y;
                Oa[i][2] += p * va.z; Oa[i][3] += p * va.w;
                Oa[i][4] += p * vb.x; Oa[i][5] += p * vb.y;
                Oa[i][6] += p * vb.z; Oa[i][7] += p * vb.w;
            }
        }
    }

    #pragma unroll
    for (int i = 0; i < 8; i++) {
        float inv = 1.0f / lrow[i];
        int srow = qt * 128 + ty * 8 + i;
        size_t base = ((size_t)(b * 16 + h) * 2048 + srow) << 7;
        uint2 h4, l4;
        split2u(Oa[i][0] * inv, Oa[i][1] * inv, h4.x, l4.x);
        split2u(Oa[i][2] * inv, Oa[i][3] * inv, h4.y, l4.y);
        *(uint2*)&oh[base + tx * 4] = h4;
        *(uint2*)&ol[base + tx * 4] = l4;
        split2u(Oa[i][4] * inv, Oa[i][5] * inv, h4.x, l4.x);
        split2u(Oa[i][6] * inv, Oa[i][7] * inv, h4.y, l4.y);
        *(uint2*)&oh[base + 64 + tx * 4] = h4;
        *(uint2*)&ol[base + 64 + tx * 4] = l4;
    }
}

// ---------------------------------------------------------------------------
extern "C" void kernel_launch(void* const* d_in, const int* in_sizes, int n_in,
                              void* d_out, int out_size)
{
    (void)in_sizes; (void)n_in; (void)out_size;
    const float* x    = (const float*)d_in[0];
    const float* wqkv = (const float*)d_in[1];
    const float* wout = (const float*)d_in[2];
    float* out = (float*)d_out;

    float* qkv_p = nullptr;
    __nv_bfloat16 *xh, *xl, *wqh, *wql, *woh, *wol, *oh, *ol;
    cudaGetSymbolAddress((void**)&qkv_p, g_qkv);
    cudaGetSymbolAddress((void**)&xh, g_xh);  cudaGetSymbolAddress((void**)&xl, g_xl);
    cudaGetSymbolAddress((void**)&wqh, g_wqh); cudaGetSymbolAddress((void**)&wql, g_wql);
    cudaGetSymbolAddress((void**)&woh, g_woh); cudaGetSymbolAddress((void**)&wol, g_wol);
    cudaGetSymbolAddress((void**)&oh, g_oh);   cudaGetSymbolAddress((void**)&ol, g_ol);

    cudaFuncSetAttribute(gemm_mma_bf16x3,
                         cudaFuncAttributeMaxDynamicSharedMemorySize, GSMEM);
    cudaFuncSetAttribute(flash_attn,
                         cudaFuncAttributeMaxDynamicSharedMemorySize, FLASH_SMEM);

    // split inputs / transpose+split weights to bf16 hi/lo
    ksplit<<<(M_TOT * GK / 4 + 255) / 256, 256>>>(x, xh, xl, M_TOT * GK / 4);
    ksplitT<<<dim3(NQKV / 32, GK / 32), dim3(32, 8)>>>(wqkv, wqh, wql, GK, NQKV);
    ksplitT<<<dim3(GK / 32, GK / 32), dim3(32, 8)>>>(wout, woh, wol, GK, GK);

    // 1) QKV projection (tensor cores, bf16x3)
    gemm_mma_bf16x3<<<dim3(NQKV / 128, M_TOT / 128), 256, GSMEM>>>(
        xh, xl, wqh, wql, qkv_p, NQKV);

    // 2) causal attention (fp32), writes bf16 hi/lo O
    flash_attn<<<dim3(16, 16, 4), 256, FLASH_SMEM>>>(qkv_p, oh, ol);

    // 3) output projection (tensor cores, bf16x3)
    gemm_mma_bf16x3<<<dim3(GK / 128, M_TOT / 128), 256, GSMEM>>>(
        oh, ol, woh, wol, out, GK);
}

// round 6
// speedup vs baseline: 2.4456x; 1.4293x over previous
#include <cuda_runtime.h>
#include <cuda_bf16.h>
#include <cstdint>
#include <math.h>

#define M_TOT 8192
#define NQKV  6144
#define GK    2048

// ---------------- device scratch ----------------
__device__ __nv_bfloat16 g_qkvh[(size_t)M_TOT * NQKV];  // QKV hi (Q pre-scaled)
__device__ __nv_bfloat16 g_qkvl[(size_t)M_TOT * NQKV];  // QKV lo
__device__ __nv_bfloat16 g_xh[(size_t)M_TOT * GK];
__device__ __nv_bfloat16 g_xl[(size_t)M_TOT * GK];
__device__ __nv_bfloat16 g_wqh[(size_t)NQKV * GK];
__device__ __nv_bfloat16 g_wql[(size_t)NQKV * GK];
__device__ __nv_bfloat16 g_woh[(size_t)GK * GK];
__device__ __nv_bfloat16 g_wol[(size_t)GK * GK];
__device__ __nv_bfloat16 g_oh[(size_t)M_TOT * GK];
__device__ __nv_bfloat16 g_ol[(size_t)M_TOT * GK];

// softmax scale * log2(e), folded into Q at GEMM1 epilogue
#define QSCALE (0.08838834764831845f * 1.4426950408889634f)

// ---------------- helpers ----------------
static __device__ __forceinline__ void split2u(float a, float b, uint32_t& h, uint32_t& l) {
    __nv_bfloat16 ha = __float2bfloat16(a);
    __nv_bfloat16 hb = __float2bfloat16(b);
    __nv_bfloat16 la = __float2bfloat16(a - __bfloat162float(ha));
    __nv_bfloat16 lb = __float2bfloat16(b - __bfloat162float(hb));
    h = (uint32_t)__bfloat16_as_ushort(ha) | ((uint32_t)__bfloat16_as_ushort(hb) << 16);
    l = (uint32_t)__bfloat16_as_ushort(la) | ((uint32_t)__bfloat16_as_ushort(lb) << 16);
}

#define CPA16(dst, src) \
    asm volatile("cp.async.cg.shared.global [%0], [%1], 16;" :: "r"(dst), "l"(src))
#define CPA_COMMIT() asm volatile("cp.async.commit_group;")
#define CPA_WAIT1()  asm volatile("cp.async.wait_group 1;")
#define CPA_WAIT0()  asm volatile("cp.async.wait_group 0;")

#define MMA16816(ac, a0, a1, a2, a3, b0, b1) \
    asm volatile("mma.sync.aligned.m16n8k16.row.col.f32.bf16.bf16.f32 " \
        "{%0,%1,%2,%3},{%4,%5,%6,%7},{%8,%9},{%0,%1,%2,%3};" \
        : "+f"((ac)[0]), "+f"((ac)[1]), "+f"((ac)[2]), "+f"((ac)[3]) \
        : "r"(a0), "r"(a1), "r"(a2), "r"(a3), "r"(b0), "r"(b1))

#define LDSM4T(r0, r1, r2, r3, addr) \
    asm volatile("ldmatrix.sync.aligned.m8n8.x4.trans.shared.b16 {%0,%1,%2,%3}, [%4];" \
        : "=r"(r0), "=r"(r1), "=r"(r2), "=r"(r3) : "r"(addr))

static __device__ __forceinline__ uint32_t lds32(uint32_t a) {
    uint32_t v;
    asm volatile("ld.shared.b32 %0, [%1];" : "=r"(v) : "r"(a));
    return v;
}

// ---------------- conversion kernels ----------------
__global__ void ksplit(const float* __restrict__ in, __nv_bfloat16* __restrict__ hi,
                       __nv_bfloat16* __restrict__ lo, int n4)
{
    int i = blockIdx.x * blockDim.x + threadIdx.x;
    if (i >= n4) return;
    float4 v = ((const float4*)in)[i];
    uint2 h, l;
    split2u(v.x, v.y, h.x, l.x);
    split2u(v.z, v.w, h.y, l.y);
    ((uint2*)hi)[i] = h;
    ((uint2*)lo)[i] = l;
}

__global__ void ksplitT(const float* __restrict__ in, __nv_bfloat16* __restrict__ hiT,
                        __nv_bfloat16* __restrict__ loT, int K, int N)
{
    __shared__ float t[32][33];
    int n0 = blockIdx.x * 32, k0 = blockIdx.y * 32;
    int tx = threadIdx.x, ty = threadIdx.y;
    #pragma unroll
    for (int j = 0; j < 32; j += 8)
        t[ty + j][tx] = in[(size_t)(k0 + ty + j) * N + n0 + tx];
    __syncthreads();
    #pragma unroll
    for (int j = 0; j < 32; j += 8) {
        float v = t[tx][ty + j];
        __nv_bfloat16 h = __float2bfloat16(v);
        __nv_bfloat16 l = __float2bfloat16(v - __bfloat162float(h));
        size_t oi = (size_t)(n0 + ty + j) * K + k0 + tx;
        hiT[oi] = h;
        loT[oi] = l;
    }
}

// ---------------- mma.sync bf16x3 GEMM ----------------
// mode 0: write fp32 C.  mode 1: write bf16 hi/lo (Cbh/Cbl), scaling cols<2048 by QSCALE.
#define SROW    80
#define TILE_B  (128 * SROW)
#define STAGE_B (4 * TILE_B)
#define GSMEM   (2 * STAGE_B)

__global__ __launch_bounds__(256)
void gemm_mma_bf16x3(const __nv_bfloat16* __restrict__ Ah,
                     const __nv_bfloat16* __restrict__ Al,
                     const __nv_bfloat16* __restrict__ Bh,
                     const __nv_bfloat16* __restrict__ Bl,
                     float* __restrict__ C,
                     __nv_bfloat16* __restrict__ Cbh,
                     __nv_bfloat16* __restrict__ Cbl,
                     int ldc, int mode)
{
    extern __shared__ __align__(16) char smem[];
    const uint32_t sbase = (uint32_t)__cvta_generic_to_shared(smem);
    const int tid  = threadIdx.x;
    const int warp = tid >> 5, lane = tid & 31;
    const int m0 = blockIdx.y * 128, n0 = blockIdx.x * 128;
    const int wm = (warp & 1) * 64, wn = (warp >> 1) * 32;

    auto issue = [&](int st, int k0) {
        uint32_t dbase = sbase + st * STAGE_B;
        #pragma unroll
        for (int t = 0; t < 8; t++) {
            int i = tid + t * 256;
            int sub = i >> 9;
            int j = i & 511;
            int r = j >> 2, c = j & 3;
            const __nv_bfloat16* g =
                (sub == 0) ? Ah + (size_t)(m0 + r) * GK + k0 + c * 8 :
                (sub == 1) ? Al + (size_t)(m0 + r) * GK + k0 + c * 8 :
                (sub == 2) ? Bh + (size_t)(n0 + r) * GK + k0 + c * 8 :
                             Bl + (size_t)(n0 + r) * GK + k0 + c * 8;
            uint32_t d = dbase + sub * TILE_B + r * SROW + c * 16;
            CPA16(d, (const void*)g);
        }
        CPA_COMMIT();
    };

    float acc[4][4][4];
    #pragma unroll
    for (int mi = 0; mi < 4; mi++)
        #pragma unroll
        for (int ni = 0; ni < 4; ni++)
            #pragma unroll
            for (int q = 0; q < 4; q++) acc[mi][ni][q] = 0.0f;

    issue(0, 0);

    const int lr = lane >> 2;
    const int lc4 = (lane & 3) * 4;

    for (int ch = 0; ch < 64; ch++) {
        int buf = ch & 1;
        if (ch < 63) { issue(buf ^ 1, (ch + 1) * 32); CPA_WAIT1(); }
        else         { CPA_WAIT0(); }
        __syncthreads();

        const char* sb  = smem + buf * STAGE_B;
        const char* sAh = sb;
        const char* sAl = sb + TILE_B;
        const char* sBh = sb + 2 * TILE_B;
        const char* sBl = sb + 3 * TILE_B;

        #pragma unroll
        for (int k16 = 0; k16 < 32; k16 += 16) {
            const int kb = k16 * 2 + lc4;
            uint32_t bh[4][2], bl[4][2];
            #pragma unroll
            for (int ni = 0; ni < 4; ni++) {
                int off = (wn + ni * 8 + lr) * SROW + kb;
                bh[ni][0] = *(const uint32_t*)(sBh + off);
                bh[ni][1] = *(const uint32_t*)(sBh + off + 16);
                bl[ni][0] = *(const uint32_t*)(sBl + off);
                bl[ni][1] = *(const uint32_t*)(sBl + off + 16);
            }
            #pragma unroll
            for (int mi = 0; mi < 4; mi++) {
                int off = (wm + mi * 16 + lr) * SROW + kb;
                uint32_t ah0 = *(const uint32_t*)(sAh + off);
                uint32_t ah1 = *(const uint32_t*)(sAh + off + 8 * SROW);
                uint32_t ah2 = *(const uint32_t*)(sAh + off + 16);
                uint32_t ah3 = *(const uint32_t*)(sAh + off + 8 * SROW + 16);
                uint32_t al0 = *(const uint32_t*)(sAl + off);
                uint32_t al1 = *(const uint32_t*)(sAl + off + 8 * SROW);
                uint32_t al2 = *(const uint32_t*)(sAl + off + 16);
                uint32_t al3 = *(const uint32_t*)(sAl + off + 8 * SROW + 16);
                #pragma unroll
                for (int ni = 0; ni < 4; ni++) {
                    MMA16816(acc[mi][ni], ah0, ah1, ah2, ah3, bh[ni][0], bh[ni][1]);
                    MMA16816(acc[mi][ni], ah0, ah1, ah2, ah3, bl[ni][0], bl[ni][1]);
                    MMA16816(acc[mi][ni], al0, al1, al2, al3, bh[ni][0], bh[ni][1]);
                }
            }
        }
        __syncthreads();
    }

    #pragma unroll
    for (int mi = 0; mi < 4; mi++) {
        int row = m0 + wm + mi * 16 + lr;
        #pragma unroll
        for (int ni = 0; ni < 4; ni++) {
            int col = n0 + wn + ni * 8 + (lane & 3) * 2;
            if (mode == 0) {
                float* p0 = C + (size_t)row * ldc + col;
                float* p1 = C + (size_t)(row + 8) * ldc + col;
                p0[0] = acc[mi][ni][0]; p0[1] = acc[mi][ni][1];
                p1[0] = acc[mi][ni][2]; p1[1] = acc[mi][ni][3];
            } else {
                float sc = (col < 2048) ? QSCALE : 1.0f;
                uint32_t h0, l0, h1, l1;
                split2u(acc[mi][ni][0] * sc, acc[mi][ni][1] * sc, h0, l0);
                split2u(acc[mi][ni][2] * sc, acc[mi][ni][3] * sc, h1, l1);
                *(uint32_t*)(Cbh + (size_t)row * ldc + col) = h0;
                *(uint32_t*)(Cbl + (size_t)row * ldc + col) = l0;
                *(uint32_t*)(Cbh + (size_t)(row + 8) * ldc + col) = h1;
                *(uint32_t*)(Cbl + (size_t)(row + 8) * ldc + col) = l1;
            }
        }
    }
}

// ---------------- flash attention with mma.sync (hi/lo bf16) ----------------
// Block = 128 q rows of one (b,h). 8 warps x 16 q-rows (warp owns full key dim).
// K processed in 64-key half-tiles, double-buffered cp.async.
// smem layout per tensor: [row][272B] (128 d bf16 = 256B + 16B pad).
#define SRA   272
#define TEN_B (128 * SRA)          // 34816
#define FSMEM (6 * TEN_B)          // 208896: Qh Ql Kh Kl Vh Vl

__global__ __launch_bounds__(256, 1)
void flash_mma(const __nv_bfloat16* __restrict__ qh, const __nv_bfloat16* __restrict__ ql,
               __nv_bfloat16* __restrict__ oh, __nv_bfloat16* __restrict__ ol)
{
    extern __shared__ __align__(16) char sm[];
    const uint32_t S0 = (uint32_t)__cvta_generic_to_shared(sm);
    const uint32_t oQh = 0, oQl = TEN_B, oKh = 2 * TEN_B, oKl = 3 * TEN_B,
                   oVh = 4 * TEN_B, oVl = 5 * TEN_B;

    const int tid = threadIdx.x, warp = tid >> 5, lane = tid & 31;
    const int lr = lane >> 2, lc = lane & 3;
    const int qt = blockIdx.x, h = blockIdx.y, b = blockIdx.z;
    const size_t rowbase = (size_t)(b * 2048 + h * 128) * 6144;

    // K/V half-tile loader: 4 tensors (Kh,Kl,Vh,Vl) x 64 rows x 16 chunks
    auto issue_kv = [&](int t64, int buf) {
        #pragma unroll
        for (int t = 0; t < 16; t++) {
            int i = tid + t * 256;
            int sub = i >> 10;                 // 0 Kh, 1 Kl, 2 Vh, 3 Vl
            int j = i & 1023;
            int r = j >> 4, c = j & 15;
            int koff = (sub >> 1) ? 4096 : 2048;
            const __nv_bfloat16* base = (sub & 1) ? ql : qh;
            const __nv_bfloat16* src = base + rowbase
                + (size_t)(t64 * 4 + (r >> 4)) * 6144 + ((r & 15) << 7) + koff + c * 8;
            uint32_t off = (sub & 1) ? ((sub >> 1) ? oVl : oKl) : ((sub >> 1) ? oVh : oKh);
            CPA16(S0 + off + (buf * 64 + r) * SRA + c * 16, src);
        }
        CPA_COMMIT();
    };

    // issue Q (group 0): 2 tensors x 128 rows x 16 chunks
    #pragma unroll
    for (int t = 0; t < 16; t++) {
        int i = tid + t * 256;
        int sub = i >> 11;
        int j = i & 2047;
        int r = j >> 4, c = j & 15;
        const __nv_bfloat16* src = (sub ? ql : qh) + rowbase
            + (size_t)(qt * 8 + (r >> 4)) * 6144 + ((r & 15) << 7) + c * 8;
        CPA16(S0 + (sub ? oQl : oQh) + r * SRA + c * 16, src);
    }
    CPA_COMMIT();

    const int nt = 2 * qt + 2;
    issue_kv(0, 0);

    float accO[16][4];
    #pragma unroll
    for (int ni = 0; ni < 16; ni++)
        #pragma unroll
        for (int q = 0; q < 4; q++) accO[ni][q] = 0.0f;
    float mrow[2] = {-1e30f, -1e30f}, lrow[2] = {0.0f, 0.0f};

    for (int t64 = 0; t64 < nt; t64++) {
        int buf = t64 & 1;
        if (t64 + 1 < nt) { issue_kv(t64 + 1, buf ^ 1); CPA_WAIT1(); }
        else              { CPA_WAIT0(); }
        __syncthreads();

        const uint32_t kbB = buf * 64 * SRA;

        // ---- S = Q @ K^T (hi/lo, 3 passes) ----
        float sacc[8][4];
        #pragma unroll
        for (int ni = 0; ni < 8; ni++)
            #pragma unroll
            for (int q = 0; q < 4; q++) sacc[ni][q] = 0.0f;

        #pragma unroll
        for (int dk = 0; dk < 8; dk++) {
            uint32_t qa = S0 + oQh + (warp * 16 + lr) * SRA + dk * 32 + lc * 4;
            uint32_t ah0 = lds32(qa);
            uint32_t ah1 = lds32(qa + 8 * SRA);
            uint32_t ah2 = lds32(qa + 16);
            uint32_t ah3 = lds32(qa + 8 * SRA + 16);
            uint32_t al0 = lds32(qa + TEN_B);
            uint32_t al1 = lds32(qa + TEN_B + 8 * SRA);
            uint32_t al2 = lds32(qa + TEN_B + 16);
            uint32_t al3 = lds32(qa + TEN_B + 8 * SRA + 16);
            #pragma unroll
            for (int ni = 0; ni < 8; ni++) {
                uint32_t ka = S0 + oKh + kbB + (ni * 8 + lr) * SRA + dk * 32 + lc * 4;
                uint32_t bh0 = lds32(ka), bh1 = lds32(ka + 16);
                uint32_t bl0 = lds32(ka + TEN_B), bl1 = lds32(ka + TEN_B + 16);
                MMA16816(sacc[ni], ah0, ah1, ah2, ah3, bh0, bh1);
                MMA16816(sacc[ni], ah0, ah1, ah2, ah3, bl0, bl1);
                MMA16816(sacc[ni], al0, al1, al2, al3, bh0, bh1);
            }
        }

        // ---- causal mask (only the last two half-tiles are partial) ----
        if (t64 >= 2 * qt) {
            #pragma unroll
            for (int ni = 0; ni < 8; ni++)
                #pragma unroll
                for (int q = 0; q < 4; q++) {
                    int col_g = t64 * 64 + ni * 8 + lc * 2 + (q & 1);
                    int row_g = qt * 128 + warp * 16 + lr + (q >> 1) * 8;
                    if (col_g > row_g) sacc[ni][q] = -1e30f;
                }
        }

        // ---- online softmax (per half: hf=0 rows lr, hf=1 rows lr+8) ----
        float corr[2];
        #pragma unroll
        for (int hf = 0; hf < 2; hf++) {
            float rm = -1e30f;
            #pragma unroll
            for (int ni = 0; ni < 8; ni++)
                rm = fmaxf(rm, fmaxf(sacc[ni][hf * 2], sacc[ni][hf * 2 + 1]));
            rm = fmaxf(rm, __shfl_xor_sync(0xffffffffu, rm, 1));
            rm = fmaxf(rm, __shfl_xor_sync(0xffffffffu, rm, 2));
            float mnew = fmaxf(mrow[hf], rm);
            corr[hf] = exp2f(mrow[hf] - mnew);
            mrow[hf] = mnew;
            float ls = 0.0f;
            #pragma unroll
            for (int ni = 0; ni < 8; ni++) {
                float p0 = exp2f(sacc[ni][hf * 2] - mnew);
                float p1 = exp2f(sacc[ni][hf * 2 + 1] - mnew);
                sacc[ni][hf * 2] = p0;
                sacc[ni][hf * 2 + 1] = p1;
                ls += p0 + p1;
            }
            lrow[hf] = lrow[hf] * corr[hf] + ls;
        }
        #pragma unroll
        for (int ni = 0; ni < 16; ni++)
            #pragma unroll
            for (int q = 0; q < 4; q++) accO[ni][q] *= corr[q >> 1];

        // ---- O += P @ V (hi/lo, 3 passes), V frags via ldmatrix.x4.trans ----
        #pragma unroll
        for (int j = 0; j < 4; j++) {
            uint32_t pah[4], pal[4];
            split2u(sacc[2 * j][0], sacc[2 * j][1], pah[0], pal[0]);
            split2u(sacc[2 * j][2], sacc[2 * j][3], pah[1], pal[1]);
            split2u(sacc[2 * j + 1][0], sacc[2 * j + 1][1], pah[2], pal[2]);
            split2u(sacc[2 * j + 1][2], sacc[2 * j + 1][3], pah[3], pal[3]);
            #pragma unroll
            for (int n2 = 0; n2 < 8; n2++) {
                uint32_t va = S0 + oVh + kbB + (j * 16 + (lane & 15)) * SRA
                            + n2 * 32 + (lane >> 4) * 16;
                uint32_t vh0, vh1, vh2, vh3, vl0, vl1, vl2, vl3;
                LDSM4T(vh0, vh1, vh2, vh3, va);
                LDSM4T(vl0, vl1, vl2, vl3, va + TEN_B);
                MMA16816(accO[2 * n2], pah[0], pah[1], pah[2], pah[3], vh0, vh1);
                MMA16816(accO[2 * n2], pal[0], pal[1], pal[2], pal[3], vh0, vh1);
                MMA16816(accO[2 * n2], pah[0], pah[1], pah[2], pah[3], vl0, vl1);
                MMA16816(accO[2 * n2 + 1], pah[0], pah[1], pah[2], pah[3], vh2, vh3);
                MMA16816(accO[2 * n2 + 1], pal[0], pal[1], pal[2], pal[3], vh2, vh3);
                MMA16816(accO[2 * n2 + 1], pah[0], pah[1], pah[2], pah[3], vl2, vl3);
            }
        }
        __syncthreads();
    }

    // ---- normalize + write O (head-contiguous layout, bf16 hi/lo) ----
    float inv[2];
    #pragma unroll
    for (int hf = 0; hf < 2; hf++) {
        float ls = lrow[hf];
        ls += __shfl_xor_sync(0xffffffffu, ls, 1);
        ls += __shfl_xor_sync(0xffffffffu, ls, 2);
        inv[hf] = 1.0f / ls;
    }
    #pragma unroll
    for (int hf = 0; hf < 2; hf++) {
        int srow = qt * 128 + warp * 16 + lr + hf * 8;
        size_t base = ((size_t)(b * 16 + h) * 2048 + srow) << 7;
        #pragma unroll
        for (int ni = 0; ni < 16; ni++) {
            int d = ni * 8 + lc * 2;
            uint32_t hh, ll;
            split2u(accO[ni][hf * 2] * inv[hf], accO[ni][hf * 2 + 1] * inv[hf], hh, ll);
            *(uint32_t*)(oh + base + d) = hh;
            *(uint32_t*)(ol + base + d) = ll;
        }
    }
}

// ---------------------------------------------------------------------------
extern "C" void kernel_launch(void* const* d_in, const int* in_sizes, int n_in,
                              void* d_out, int out_size)
{
    (void)in_sizes; (void)n_in; (void)out_size;
    const float* x    = (const float*)d_in[0];
    const float* wqkv = (const float*)d_in[1];
    const float* wout = (const float*)d_in[2];
    float* out = (float*)d_out;

    __nv_bfloat16 *qkvh, *qkvl, *xh, *xl, *wqh, *wql, *woh, *wol, *oh, *ol;
    cudaGetSymbolAddress((void**)&qkvh, g_qkvh); cudaGetSymbolAddress((void**)&qkvl, g_qkvl);
    cudaGetSymbolAddress((void**)&xh, g_xh);     cudaGetSymbolAddress((void**)&xl, g_xl);
    cudaGetSymbolAddress((void**)&wqh, g_wqh);   cudaGetSymbolAddress((void**)&wql, g_wql);
    cudaGetSymbolAddress((void**)&woh, g_woh);   cudaGetSymbolAddress((void**)&wol, g_wol);
    cudaGetSymbolAddress((void**)&oh, g_oh);     cudaGetSymbolAddress((void**)&ol, g_ol);

    cudaFuncSetAttribute(gemm_mma_bf16x3,
                         cudaFuncAttributeMaxDynamicSharedMemorySize, GSMEM);
    cudaFuncSetAttribute(flash_mma,
                         cudaFuncAttributeMaxDynamicSharedMemorySize, FSMEM);

    ksplit<<<(M_TOT * GK / 4 + 255) / 256, 256>>>(x, xh, xl, M_TOT * GK / 4);
    ksplitT<<<dim3(NQKV / 32, GK / 32), dim3(32, 8)>>>(wqkv, wqh, wql, GK, NQKV);
    ksplitT<<<dim3(GK / 32, GK / 32), dim3(32, 8)>>>(wout, woh, wol, GK, GK);

    // 1) QKV projection -> bf16 hi/lo (Q pre-scaled)
    gemm_mma_bf16x3<<<dim3(NQKV / 128, M_TOT / 128), 256, GSMEM>>>(
        xh, xl, wqh, wql, nullptr, qkvh, qkvl, NQKV, 1);

    // 2) causal attention on tensor cores (hi/lo), writes bf16 hi/lo O
    flash_mma<<<dim3(16, 16, 4), 256, FSMEM>>>(qkvh, qkvl, oh, ol);

    // 3) output projection -> fp32 out
    gemm_mma_bf16x3<<<dim3(GK / 128, M_TOT / 128), 256, GSMEM>>>(
        oh, ol, woh, wol, out, nullptr, nullptr, GK, 0);
}

// round 7
// speedup vs baseline: 2.7436x; 1.1219x over previous
#include <cuda_runtime.h>
#include <cuda_bf16.h>
#include <cuda_fp16.h>
#include <cstdint>
#include <math.h>

#define M_TOT 8192
#define NQKV  6144
#define GK    2048

// ---------------- device scratch ----------------
__device__ __nv_bfloat16 g_qkvh[(size_t)M_TOT * NQKV];  // Q,K bf16 hi | V fp16 hi
__device__ __nv_bfloat16 g_qkvl[(size_t)M_TOT * NQKV];  // Q,K bf16 lo | V fp16 lo
__device__ __nv_bfloat16 g_xh[(size_t)M_TOT * GK];
__device__ __nv_bfloat16 g_xl[(size_t)M_TOT * GK];
__device__ __nv_bfloat16 g_wqh[(size_t)NQKV * GK];
__device__ __nv_bfloat16 g_wql[(size_t)NQKV * GK];
__device__ __nv_bfloat16 g_woh[(size_t)GK * GK];
__device__ __nv_bfloat16 g_wol[(size_t)GK * GK];
__device__ __nv_bfloat16 g_oh[(size_t)M_TOT * GK];
__device__ __nv_bfloat16 g_ol[(size_t)M_TOT * GK];

#define QSCALE (0.08838834764831845f * 1.4426950408889634f)

// ---------------- helpers ----------------
static __device__ __forceinline__ void split2u(float a, float b, uint32_t& h, uint32_t& l) {
    __nv_bfloat16 ha = __float2bfloat16(a);
    __nv_bfloat16 hb = __float2bfloat16(b);
    __nv_bfloat16 la = __float2bfloat16(a - __bfloat162float(ha));
    __nv_bfloat16 lb = __float2bfloat16(b - __bfloat162float(hb));
    h = (uint32_t)__bfloat16_as_ushort(ha) | ((uint32_t)__bfloat16_as_ushort(hb) << 16);
    l = (uint32_t)__bfloat16_as_ushort(la) | ((uint32_t)__bfloat16_as_ushort(lb) << 16);
}
static __device__ __forceinline__ void split2h(float a, float b, uint32_t& h, uint32_t& l) {
    __half ha = __float2half(a);
    __half hb = __float2half(b);
    __half la = __float2half(a - __half2float(ha));
    __half lb = __float2half(b - __half2float(hb));
    h = (uint32_t)__half_as_ushort(ha) | ((uint32_t)__half_as_ushort(hb) << 16);
    l = (uint32_t)__half_as_ushort(la) | ((uint32_t)__half_as_ushort(lb) << 16);
}

#define CPA16(dst, src) \
    asm volatile("cp.async.cg.shared.global [%0], [%1], 16;" :: "r"(dst), "l"(src))
#define CPA_COMMIT() asm volatile("cp.async.commit_group;")
#define CPA_WAIT1()  asm volatile("cp.async.wait_group 1;")
#define CPA_WAIT0()  asm volatile("cp.async.wait_group 0;")

#define MMA16816(ac, a0, a1, a2, a3, b0, b1) \
    asm volatile("mma.sync.aligned.m16n8k16.row.col.f32.bf16.bf16.f32 " \
        "{%0,%1,%2,%3},{%4,%5,%6,%7},{%8,%9},{%0,%1,%2,%3};" \
        : "+f"((ac)[0]), "+f"((ac)[1]), "+f"((ac)[2]), "+f"((ac)[3]) \
        : "r"(a0), "r"(a1), "r"(a2), "r"(a3), "r"(b0), "r"(b1))

#define MMAH16816(ac, a0, a1, a2, a3, b0, b1) \
    asm volatile("mma.sync.aligned.m16n8k16.row.col.f32.f16.f16.f32 " \
        "{%0,%1,%2,%3},{%4,%5,%6,%7},{%8,%9},{%0,%1,%2,%3};" \
        : "+f"((ac)[0]), "+f"((ac)[1]), "+f"((ac)[2]), "+f"((ac)[3]) \
        : "r"(a0), "r"(a1), "r"(a2), "r"(a3), "r"(b0), "r"(b1))

#define LDSM4(r0, r1, r2, r3, addr) \
    asm volatile("ldmatrix.sync.aligned.m8n8.x4.shared.b16 {%0,%1,%2,%3}, [%4];" \
        : "=r"(r0), "=r"(r1), "=r"(r2), "=r"(r3) : "r"(addr))
#define LDSM4T(r0, r1, r2, r3, addr) \
    asm volatile("ldmatrix.sync.aligned.m8n8.x4.trans.shared.b16 {%0,%1,%2,%3}, [%4];" \
        : "=r"(r0), "=r"(r1), "=r"(r2), "=r"(r3) : "r"(addr))

// pack two fp32 -> fp16x2 (lo = first arg's second operand)
#define PACKH(d, hi, lo) \
    asm("cvt.rn.f16x2.f32 %0, %1, %2;" : "=r"(d) : "f"(hi), "f"(lo))

// ---------------- conversion kernels ----------------
__global__ void ksplit(const float* __restrict__ in, __nv_bfloat16* __restrict__ hi,
                       __nv_bfloat16* __restrict__ lo, int n4)
{
    int i = blockIdx.x * blockDim.x + threadIdx.x;
    if (i >= n4) return;
    float4 v = ((const float4*)in)[i];
    uint2 h, l;
    split2u(v.x, v.y, h.x, l.x);
    split2u(v.z, v.w, h.y, l.y);
    ((uint2*)hi)[i] = h;
    ((uint2*)lo)[i] = l;
}

__global__ void ksplitT(const float* __restrict__ in, __nv_bfloat16* __restrict__ hiT,
                        __nv_bfloat16* __restrict__ loT, int K, int N)
{
    __shared__ float t[32][33];
    int n0 = blockIdx.x * 32, k0 = blockIdx.y * 32;
    int tx = threadIdx.x, ty = threadIdx.y;
    #pragma unroll
    for (int j = 0; j < 32; j += 8)
        t[ty + j][tx] = in[(size_t)(k0 + ty + j) * N + n0 + tx];
    __syncthreads();
    #pragma unroll
    for (int j = 0; j < 32; j += 8) {
        float v = t[tx][ty + j];
        __nv_bfloat16 h = __float2bfloat16(v);
        __nv_bfloat16 l = __float2bfloat16(v - __bfloat162float(h));
        size_t oi = (size_t)(n0 + ty + j) * K + k0 + tx;
        hiT[oi] = h;
        loT[oi] = l;
    }
}

// ---------------- mma.sync bf16x3 GEMM ----------------
// mode 0: fp32 C. mode 1: QKV epilogue — col<2048 bf16 split * QSCALE,
// col<4096 bf16 split, col>=4096 fp16 split (V).
#define SROW    80
#define TILE_B  (128 * SROW)
#define STAGE_B (4 * TILE_B)
#define GSMEM   (2 * STAGE_B)

__global__ __launch_bounds__(256)
void gemm_mma_bf16x3(const __nv_bfloat16* __restrict__ Ah,
                     const __nv_bfloat16* __restrict__ Al,
                     const __nv_bfloat16* __restrict__ Bh,
                     const __nv_bfloat16* __restrict__ Bl,
                     float* __restrict__ C,
                     __nv_bfloat16* __restrict__ Cbh,
                     __nv_bfloat16* __restrict__ Cbl,
                     int ldc, int mode)
{
    extern __shared__ __align__(16) char smem[];
    const uint32_t sbase = (uint32_t)__cvta_generic_to_shared(smem);
    const int tid  = threadIdx.x;
    const int warp = tid >> 5, lane = tid & 31;
    const int m0 = blockIdx.y * 128, n0 = blockIdx.x * 128;
    const int wm = (warp & 1) * 64, wn = (warp >> 1) * 32;

    auto issue = [&](int st, int k0) {
        uint32_t dbase = sbase + st * STAGE_B;
        #pragma unroll
        for (int t = 0; t < 8; t++) {
            int i = tid + t * 256;
            int sub = i >> 9;
            int j = i & 511;
            int r = j >> 2, c = j & 3;
            const __nv_bfloat16* g =
                (sub == 0) ? Ah + (size_t)(m0 + r) * GK + k0 + c * 8 :
                (sub == 1) ? Al + (size_t)(m0 + r) * GK + k0 + c * 8 :
                (sub == 2) ? Bh + (size_t)(n0 + r) * GK + k0 + c * 8 :
                             Bl + (size_t)(n0 + r) * GK + k0 + c * 8;
            uint32_t d = dbase + sub * TILE_B + r * SROW + c * 16;
            CPA16(d, (const void*)g);
        }
        CPA_COMMIT();
    };

    float acc[4][4][4];
    #pragma unroll
    for (int mi = 0; mi < 4; mi++)
        #pragma unroll
        for (int ni = 0; ni < 4; ni++)
            #pragma unroll
            for (int q = 0; q < 4; q++) acc[mi][ni][q] = 0.0f;

    issue(0, 0);

    const int lr = lane >> 2;
    // ldmatrix lane-address components
    const int arow = lane & 15, ahalf = (lane >> 4) * 16;          // A frags
    const int brow = (lane & 7) + ((lane >> 4) << 3);              // B frags
    const int bhalf = ((lane >> 3) & 1) * 16;

    for (int ch = 0; ch < 64; ch++) {
        int buf = ch & 1;
        if (ch < 63) { issue(buf ^ 1, (ch + 1) * 32); CPA_WAIT1(); }
        else         { CPA_WAIT0(); }
        __syncthreads();

        const uint32_t sb  = sbase + buf * STAGE_B;
        const uint32_t sAh = sb, sAl = sb + TILE_B;
        const uint32_t sBh = sb + 2 * TILE_B, sBl = sb + 3 * TILE_B;

        #pragma unroll
        for (int k16 = 0; k16 < 32; k16 += 16) {
            const int kb2 = k16 * 2;
            uint32_t bh[4][2], bl[4][2];
            #pragma unroll
            for (int np = 0; np < 2; np++) {
                uint32_t ba = (wn + np * 16 + brow) * SROW + kb2 + bhalf;
                LDSM4(bh[2 * np][0], bh[2 * np][1], bh[2 * np + 1][0], bh[2 * np + 1][1],
                      sBh + ba);
                LDSM4(bl[2 * np][0], bl[2 * np][1], bl[2 * np + 1][0], bl[2 * np + 1][1],
                      sBl + ba);
            }
            #pragma unroll
            for (int mi = 0; mi < 4; mi++) {
                uint32_t aa = (wm + mi * 16 + arow) * SROW + kb2 + ahalf;
                uint32_t ah0, ah1, ah2, ah3, al0, al1, al2, al3;
                LDSM4(ah0, ah1, ah2, ah3, sAh + aa);
                LDSM4(al0, al1, al2, al3, sAl + aa);
                #pragma unroll
                for (int ni = 0; ni < 4; ni++) {
                    MMA16816(acc[mi][ni], ah0, ah1, ah2, ah3, bh[ni][0], bh[ni][1]);
                    MMA16816(acc[mi][ni], ah0, ah1, ah2, ah3, bl[ni][0], bl[ni][1]);
                    MMA16816(acc[mi][ni], al0, al1, al2, al3, bh[ni][0], bh[ni][1]);
                }
            }
        }
        __syncthreads();
    }

    #pragma unroll
    for (int mi = 0; mi < 4; mi++) {
        int row = m0 + wm + mi * 16 + lr;
        #pragma unroll
        for (int ni = 0; ni < 4; ni++) {
            int col = n0 + wn + ni * 8 + (lane & 3) * 2;
            if (mode == 0) {
                float* p0 = C + (size_t)row * ldc + col;
                float* p1 = C + (size_t)(row + 8) * ldc + col;
                p0[0] = acc[mi][ni][0]; p0[1] = acc[mi][ni][1];
                p1[0] = acc[mi][ni][2]; p1[1] = acc[mi][ni][3];
            } else {
                uint32_t h0, l0, h1, l1;
                if (col >= 4096) {          // V -> fp16 split
                    split2h(acc[mi][ni][0], acc[mi][ni][1], h0, l0);
                    split2h(acc[mi][ni][2], acc[mi][ni][3], h1, l1);
                } else {                    // Q (scaled) / K -> bf16 split
                    float sc = (col < 2048) ? QSCALE : 1.0f;
                    split2u(acc[mi][ni][0] * sc, acc[mi][ni][1] * sc, h0, l0);
                    split2u(acc[mi][ni][2] * sc, acc[mi][ni][3] * sc, h1, l1);
                }
                *(uint32_t*)(Cbh + (size_t)row * ldc + col) = h0;
                *(uint32_t*)(Cbl + (size_t)row * ldc + col) = l0;
                *(uint32_t*)(Cbh + (size_t)(row + 8) * ldc + col) = h1;
                *(uint32_t*)(Cbl + (size_t)(row + 8) * ldc + col) = l1;
            }
        }
    }
}

// ---------------- flash attention (mma.sync) ----------------
// Q,K bf16 hi/lo (3 S-passes); P fp16 single; V fp16 hi/lo (2 PV-passes).
#define SRA   272
#define TEN_B (128 * SRA)
#define FSMEM (6 * TEN_B)

__global__ __launch_bounds__(256, 1)
void flash_mma(const __nv_bfloat16* __restrict__ qh, const __nv_bfloat16* __restrict__ ql,
               __nv_bfloat16* __restrict__ oh, __nv_bfloat16* __restrict__ ol)
{
    extern __shared__ __align__(16) char sm[];
    const uint32_t S0 = (uint32_t)__cvta_generic_to_shared(sm);
    const uint32_t oQh = 0, oQl = TEN_B, oKh = 2 * TEN_B, oKl = 3 * TEN_B,
                   oVh = 4 * TEN_B, oVl = 5 * TEN_B;

    const int tid = threadIdx.x, warp = tid >> 5, lane = tid & 31;
    const int lr = lane >> 2, lc = lane & 3;
    const int qt = blockIdx.x, h = blockIdx.y, b = blockIdx.z;
    const size_t rowbase = (size_t)(b * 2048 + h * 128) * 6144;

    const int arow = lane & 15, ahalf = (lane >> 4) * 16;
    const int brow = (lane & 7) + ((lane >> 4) << 3);
    const int bhalf = ((lane >> 3) & 1) * 16;

    auto issue_kv = [&](int t64, int buf) {
        #pragma unroll
        for (int t = 0; t < 16; t++) {
            int i = tid + t * 256;
            int sub = i >> 10;
            int j = i & 1023;
            int r = j >> 4, c = j & 15;
            int koff = (sub >> 1) ? 4096 : 2048;
            const __nv_bfloat16* base = (sub & 1) ? ql : qh;
            const __nv_bfloat16* src = base + rowbase
                + (size_t)(t64 * 4 + (r >> 4)) * 6144 + ((r & 15) << 7) + koff + c * 8;
            uint32_t off = (sub & 1) ? ((sub >> 1) ? oVl : oKl) : ((sub >> 1) ? oVh : oKh);
            CPA16(S0 + off + (buf * 64 + r) * SRA + c * 16, src);
        }
        CPA_COMMIT();
    };

    #pragma unroll
    for (int t = 0; t < 16; t++) {
        int i = tid + t * 256;
        int sub = i >> 11;
        int j = i & 2047;
        int r = j >> 4, c = j & 15;
        const __nv_bfloat16* src = (sub ? ql : qh) + rowbase
            + (size_t)(qt * 8 + (r >> 4)) * 6144 + ((r & 15) << 7) + c * 8;
        CPA16(S0 + (sub ? oQl : oQh) + r * SRA + c * 16, src);
    }
    CPA_COMMIT();

    const int nt = 2 * qt + 2;
    issue_kv(0, 0);

    float accO[16][4];
    #pragma unroll
    for (int ni = 0; ni < 16; ni++)
        #pragma unroll
        for (int q = 0; q < 4; q++) accO[ni][q] = 0.0f;
    float mrow[2] = {-1e30f, -1e30f}, lrow[2] = {0.0f, 0.0f};

    for (int t64 = 0; t64 < nt; t64++) {
        int buf = t64 & 1;
        if (t64 + 1 < nt) { issue_kv(t64 + 1, buf ^ 1); CPA_WAIT1(); }
        else              { CPA_WAIT0(); }
        __syncthreads();

        const uint32_t kbB = buf * 64 * SRA;

        // ---- S = Q @ K^T (bf16 hi/lo, 3 passes) ----
        float sacc[8][4];
        #pragma unroll
        for (int ni = 0; ni < 8; ni++)
            #pragma unroll
            for (int q = 0; q < 4; q++) sacc[ni][q] = 0.0f;

        #pragma unroll
        for (int dk = 0; dk < 8; dk++) {
            uint32_t qa = S0 + oQh + (warp * 16 + arow) * SRA + dk * 32 + ahalf;
            uint32_t ah0, ah1, ah2, ah3, al0, al1, al2, al3;
            LDSM4(ah0, ah1, ah2, ah3, qa);
            LDSM4(al0, al1, al2, al3, qa + TEN_B);
            #pragma unroll
            for (int np = 0; np < 4; np++) {
                uint32_t ka = S0 + oKh + kbB + (np * 16 + brow) * SRA + dk * 32 + bhalf;
                uint32_t bh0, bh1, bh2, bh3, bl0, bl1, bl2, bl3;
                LDSM4(bh0, bh1, bh2, bh3, ka);
                LDSM4(bl0, bl1, bl2, bl3, ka + TEN_B);
                MMA16816(sacc[2 * np], ah0, ah1, ah2, ah3, bh0, bh1);
                MMA16816(sacc[2 * np], ah0, ah1, ah2, ah3, bl0, bl1);
                MMA16816(sacc[2 * np], al0, al1, al2, al3, bh0, bh1);
                MMA16816(sacc[2 * np + 1], ah0, ah1, ah2, ah3, bh2, bh3);
                MMA16816(sacc[2 * np + 1], ah0, ah1, ah2, ah3, bl2, bl3);
                MMA16816(sacc[2 * np + 1], al0, al1, al2, al3, bh2, bh3);
            }
        }

        // ---- causal mask ----
        if (t64 >= 2 * qt) {
            #pragma unroll
            for (int ni = 0; ni < 8; ni++)
                #pragma unroll
                for (int q = 0; q < 4; q++) {
                    int col_g = t64 * 64 + ni * 8 + lc * 2 + (q & 1);
                    int row_g = qt * 128 + warp * 16 + lr + (q >> 1) * 8;
                    if (col_g > row_g) sacc[ni][q] = -1e30f;
                }
        }

        // ---- online softmax ----
        float corr[2];
        #pragma unroll
        for (int hf = 0; hf < 2; hf++) {
            float rm = -1e30f;
            #pragma unroll
            for (int ni = 0; ni < 8; ni++)
                rm = fmaxf(rm, fmaxf(sacc[ni][hf * 2], sacc[ni][hf * 2 + 1]));
            rm = fmaxf(rm, __shfl_xor_sync(0xffffffffu, rm, 1));
            rm = fmaxf(rm, __shfl_xor_sync(0xffffffffu, rm, 2));
            float mnew = fmaxf(mrow[hf], rm);
            corr[hf] = exp2f(mrow[hf] - mnew);
            mrow[hf] = mnew;
            float ls = 0.0f;
            #pragma unroll
            for (int ni = 0; ni < 8; ni++) {
                float p0 = exp2f(sacc[ni][hf * 2] - mnew);
                float p1 = exp2f(sacc[ni][hf * 2 + 1] - mnew);
                sacc[ni][hf * 2] = p0;
                sacc[ni][hf * 2 + 1] = p1;
                ls += p0 + p1;
            }
            lrow[hf] = lrow[hf] * corr[hf] + ls;
        }
        #pragma unroll
        for (int ni = 0; ni < 16; ni++)
            #pragma unroll
            for (int q = 0; q < 4; q++) accO[ni][q] *= corr[q >> 1];

        // ---- O += P @ V (P fp16 single, V fp16 hi/lo -> 2 passes) ----
        #pragma unroll
        for (int j = 0; j < 4; j++) {
            uint32_t pa0, pa1, pa2, pa3;
            PACKH(pa0, sacc[2 * j][1], sacc[2 * j][0]);
            PACKH(pa1, sacc[2 * j][3], sacc[2 * j][2]);
            PACKH(pa2, sacc[2 * j + 1][1], sacc[2 * j + 1][0]);
            PACKH(pa3, sacc[2 * j + 1][3], sacc[2 * j + 1][2]);
            #pragma unroll
            for (int n2 = 0; n2 < 8; n2++) {
                uint32_t va = S0 + oVh + kbB + (j * 16 + (lane & 15)) * SRA
                            + n2 * 32 + (lane >> 4) * 16;
                uint32_t vh0, vh1, vh2, vh3, vl0, vl1, vl2, vl3;
                LDSM4T(vh0, vh1, vh2, vh3, va);
                LDSM4T(vl0, vl1, vl2, vl3, va + TEN_B);
                MMAH16816(accO[2 * n2], pa0, pa1, pa2, pa3, vh0, vh1);
                MMAH16816(accO[2 * n2], pa0, pa1, pa2, pa3, vl0, vl1);
                MMAH16816(accO[2 * n2 + 1], pa0, pa1, pa2, pa3, vh2, vh3);
                MMAH16816(accO[2 * n2 + 1], pa0, pa1, pa2, pa3, vl2, vl3);
            }
        }
        __syncthreads();
    }

    // ---- normalize + write O (bf16 hi/lo, head-contiguous) ----
    float inv[2];
    #pragma unroll
    for (int hf = 0; hf < 2; hf++) {
        float ls = lrow[hf];
        ls += __shfl_xor_sync(0xffffffffu, ls, 1);
        ls += __shfl_xor_sync(0xffffffffu, ls, 2);
        inv[hf] = 1.0f / ls;
    }
    #pragma unroll
    for (int hf = 0; hf < 2; hf++) {
        int srow = qt * 128 + warp * 16 + lr + hf * 8;
        size_t base = ((size_t)(b * 16 + h) * 2048 + srow) << 7;
        #pragma unroll
        for (int ni = 0; ni < 16; ni++) {
            int d = ni * 8 + lc * 2;
            uint32_t hh, ll;
            split2u(accO[ni][hf * 2] * inv[hf], accO[ni][hf * 2 + 1] * inv[hf], hh, ll);
            *(uint32_t*)(oh + base + d) = hh;
            *(uint32_t*)(ol + base + d) = ll;
        }
    }
}

// ---------------------------------------------------------------------------
extern "C" void kernel_launch(void* const* d_in, const int* in_sizes, int n_in,
                              void* d_out, int out_size)
{
    (void)in_sizes; (void)n_in; (void)out_size;
    const float* x    = (const float*)d_in[0];
    const float* wqkv = (const float*)d_in[1];
    const float* wout = (const float*)d_in[2];
    float* out = (float*)d_out;

    __nv_bfloat16 *qkvh, *qkvl, *xh, *xl, *wqh, *wql, *woh, *wol, *oh, *ol;
    cudaGetSymbolAddress((void**)&qkvh, g_qkvh); cudaGetSymbolAddress((void**)&qkvl, g_qkvl);
    cudaGetSymbolAddress((void**)&xh, g_xh);     cudaGetSymbolAddress((void**)&xl, g_xl);
    cudaGetSymbolAddress((void**)&wqh, g_wqh);   cudaGetSymbolAddress((void**)&wql, g_wql);
    cudaGetSymbolAddress((void**)&woh, g_woh);   cudaGetSymbolAddress((void**)&wol, g_wol);
    cudaGetSymbolAddress((void**)&oh, g_oh);     cudaGetSymbolAddress((void**)&ol, g_ol);

    cudaFuncSetAttribute(gemm_mma_bf16x3,
                         cudaFuncAttributeMaxDynamicSharedMemorySize, GSMEM);
    cudaFuncSetAttribute(flash_mma,
                         cudaFuncAttributeMaxDynamicSharedMemorySize, FSMEM);

    ksplit<<<(M_TOT * GK / 4 + 255) / 256, 256>>>(x, xh, xl, M_TOT * GK / 4);
    ksplitT<<<dim3(NQKV / 32, GK / 32), dim3(32, 8)>>>(wqkv, wqh, wql, GK, NQKV);
    ksplitT<<<dim3(GK / 32, GK / 32), dim3(32, 8)>>>(wout, woh, wol, GK, GK);

    gemm_mma_bf16x3<<<dim3(NQKV / 128, M_TOT / 128), 256, GSMEM>>>(
        xh, xl, wqh, wql, nullptr, qkvh, qkvl, NQKV, 1);

    flash_mma<<<dim3(16, 16, 4), 256, FSMEM>>>(qkvh, qkvl, oh, ol);

    gemm_mma_bf16x3<<<dim3(GK / 128, M_TOT / 128), 256, GSMEM>>>(
        oh, ol, woh, wol, out, nullptr, nullptr, GK, 0);
}